// round 13
// baseline (speedup 1.0000x reference)
#include <cuda_runtime.h>
#include <cuda_fp16.h>
#include <cstdint>

// ===========================================================================
// CIN (xDeepFM) on GB300 via mma.sync fp16 (f32 accum).
// Layers 1-2: generated-A GEMM at M=16384 (chunk-paired K=80 = 5 x m16n8k16,
//   147 CTAs / BM=112 / 16 warps, R8 warp table; 5-stage cp.async pipeline,
//   one wait+syncthreads per TWO pairs).
// Layer 3 collapsed: out3[b,n] = sum_k S2[b,k] W2[k,n],
//   S2[b, j*40+i] = sum_d X[b,i,d] H2[b,j,d].
//   R12: s2 split 4x per b (grid 2048, 11.4 KB smem) — was latency-bound at
//   38.9 us with one 45-KB CTA per b.
//   final3 = M=512 GEMM, 4-way K-split, f32 partials summed in reduce_out.
// ===========================================================================

constexpr int MT  = 16384;
constexpr int F0  = 40;
constexpr int BM  = 112;
constexpr int NT  = 25;

constexpr int STG_BW   = NT * 32 * 12;        // B words per pair-stage = 9600
constexpr int STG_BB   = STG_BW * 4;          // 38400 B
constexpr int GRID     = 147;

__device__ float g_Xt [F0  * MT + 256];
__device__ float g_Ht1[200 * MT + 256];
__device__ float g_Ht2[200 * MT + 256];
__device__ __align__(16) __half g_S2[512 * 8000];
__device__ float g_P3[4 * 512 * 200];
__device__ __align__(16) uint32_t g_B0[20  * STG_BW];
__device__ __align__(16) uint32_t g_B1[100 * STG_BW];
__device__ __align__(16) uint32_t g_B2[100 * STG_BW];

// R8 warp table: (m16 tile, nt0, cnt); SMSP unit sums (wid%4): 45,45,43,42
__constant__ int c_tile[16] = {2,3,4,5, 2,3,6,4, 5,6,0,1, 0,0,1,1};
__constant__ int c_nt0 [16] = {0,0,0,0, 13,13,0,13, 13,13,0,0, 9,17,9,17};
__constant__ int c_cnt [16] = {13,13,13,13, 12,12,13,12, 12,12,9,9, 8,8,8,8};

// ---------------------------------------------------------------- helpers
__device__ __forceinline__ uint32_t smem_u32(const void* p) {
    uint32_t a;
    asm("{ .reg .u64 t; cvta.to.shared.u64 t, %1; cvt.u32.u64 %0, t; }"
        : "=r"(a) : "l"(p));
    return a;
}

__device__ __forceinline__ uint32_t pack_h2(float lo, float hi) {
    uint32_t u;
    asm("cvt.rn.f16x2.f32 %0, %1, %2;" : "=r"(u) : "f"(hi), "f"(lo));
    return u;
}

__device__ __forceinline__ void cp16(uint32_t dst_smem, const void* src) {
    asm volatile("cp.async.cg.shared.global [%0], [%1], 16;"
                 :: "r"(dst_smem), "l"(src) : "memory");
}

__device__ __forceinline__ void mma16(float* d,
                                      uint32_t a0, uint32_t a1, uint32_t a2, uint32_t a3,
                                      uint32_t b0, uint32_t b1) {
    asm volatile(
        "mma.sync.aligned.m16n8k16.row.col.f32.f16.f16.f32 "
        "{%0,%1,%2,%3}, {%4,%5,%6,%7}, {%8,%9}, {%0,%1,%2,%3};"
        : "+f"(d[0]), "+f"(d[1]), "+f"(d[2]), "+f"(d[3])
        : "r"(a0), "r"(a1), "r"(a2), "r"(a3), "r"(b0), "r"(b1));
}

// ---------------------------------------------------------------- fused prep
__global__ void prep_all_kernel(const float* __restrict__ inp,
                                const float* __restrict__ W0,
                                const float* __restrict__ W1,
                                const float* __restrict__ W2,
                                uint32_t* __restrict__ B0,
                                uint32_t* __restrict__ B1,
                                uint32_t* __restrict__ B2) {
    int idx = blockIdx.x * blockDim.x + threadIdx.x;
    if (idx < F0 * MT) {
        int i = idx >> 14;
        int m = idx & (MT - 1);
        int b = m >> 5, d = m & 31;
        g_Xt[idx] = inp[b * (F0 * 32) + i * 32 + d];
        return;
    }
    idx -= F0 * MT;
    if (idx >= 220 * STG_BW) return;
    int v = idx % 12;
    int t = idx / 12;
    int lane = t & 31; t >>= 5;
    int nt   = t % NT;
    int pg   = t / NT;

    const float* W; uint32_t* blob; int FI, p;
    if (pg < 20)       { W = W0; blob = B0; FI = 40;  p = pg; }
    else if (pg < 120) { W = W1; blob = B1; FI = 200; p = pg - 20; }
    else               { W = W2; blob = B2; FI = 200; p = pg - 120; }

    uint32_t word = 0;
    if (v < 10) {
        int u = (v < 5) ? v : v - 5;
        int j = 2 * p + (v >= 5);
        int n  = nt * 8 + (lane >> 2);
        int i0 = u * 8 + (lane & 3) * 2;
        float lo = __ldg(&W[((size_t)i0 * FI + j) * 200 + n]);
        float hi = __ldg(&W[((size_t)(i0 + 1) * FI + j) * 200 + n]);
        word = pack_h2(lo, hi);
    }
    blob[(((size_t)p * NT + nt) * 32 + lane) * 12 + v] = word;
}

// ---------------------------------------------------------------- layer 1/2
// smem: bstg 5*38400 | xs[BM][40] 17920 | hstg[5][2][BM] 4480  = 214400 B
template <int CH>
__global__ __launch_bounds__(512, 1)
void cin_fp16_layer(const float* __restrict__ Hprev,    // [CH][MT]
                    const uint32_t* __restrict__ blob,  // [CHP][STG_BW]
                    float* __restrict__ Hout)           // [200][MT]
{
    constexpr int CHP = CH / 2;
    extern __shared__ __align__(16) char smem[];
    uint32_t* bstg = (uint32_t*)smem;
    float*    xs   = (float*)(smem + 5 * STG_BB);
    float*    hstg = (float*)(smem + 5 * STG_BB + 17920);

    const int tid  = threadIdx.x;
    const int lane = tid & 31;
    const int wid  = tid >> 5;
    const int g    = lane >> 2;
    const int t4   = lane & 3;
    const int m0   = blockIdx.x * BM;

    const int tile = c_tile[wid];
    const int nt0  = c_nt0[wid];
    const int cnt  = c_cnt[wid];
    const int row0 = tile * 16 + g;

    for (int idx = tid; idx < BM * 40; idx += 512) {
        int ml = idx / 40, i = idx - ml * 40;
        int gr = m0 + ml; if (gr > MT - 1) gr = MT - 1;
        xs[ml * 40 + i] = g_Xt[i * MT + gr];
    }

    const uint32_t uB = smem_u32(bstg);
    const uint32_t uH = smem_u32(hstg);

    auto issue = [&](int p, int s) {
        const char* srcB = (const char*)(blob + (size_t)p * STG_BW);
        uint32_t dB = uB + s * STG_BB;
        for (int t = tid * 16; t < STG_BB; t += 512 * 16)
            cp16(dB + t, srcB + t);
        if (tid < 56) {
            int cc = tid / 28, q = tid - cc * 28;
            cp16(uH + s * (2 * BM * 4) + cc * (BM * 4) + q * 16,
                 (const char*)(Hprev + (size_t)(2 * p + cc) * MT + m0) + q * 16);
        }
    };

    issue(0, 0);
    asm volatile("cp.async.commit_group;" ::: "memory");
    issue(1, 1);
    asm volatile("cp.async.commit_group;" ::: "memory");
    issue(2, 2);
    asm volatile("cp.async.commit_group;" ::: "memory");

    float acc[13][4];
#pragma unroll
    for (int q = 0; q < 13; q++)
#pragma unroll
        for (int c = 0; c < 4; c++) acc[q][c] = 0.0f;

    auto consume = [&](int s) {
        const float* hp = hstg + s * (2 * BM);
        const float hA0 = hp[row0],      hA1 = hp[row0 + 8];
        const float hB0 = hp[BM + row0], hB1 = hp[BM + row0 + 8];

        uint32_t P0[10], P1[10];
#pragma unroll
        for (int pb = 0; pb < 5; pb++) {
            const int ib = pb * 8 + 2 * t4;
            float2 x0 = *(const float2*)(xs + row0 * 40 + ib);
            float2 x1 = *(const float2*)(xs + (row0 + 8) * 40 + ib);
            P0[pb]     = pack_h2(x0.x * hA0, x0.y * hA0);
            P1[pb]     = pack_h2(x1.x * hA1, x1.y * hA1);
            P0[5 + pb] = pack_h2(x0.x * hB0, x0.y * hB0);
            P1[5 + pb] = pack_h2(x1.x * hB1, x1.y * hB1);
        }

        const uint32_t* bs = bstg + s * STG_BW;
#pragma unroll
        for (int q = 0; q < 13; q++) {
            if (q < cnt) {
                const uint4* bw = (const uint4*)(bs + ((nt0 + q) * 32 + lane) * 12);
                uint4 w0 = bw[0], w1 = bw[1], w2 = bw[2];
                mma16(acc[q], P0[0], P1[0], P0[1], P1[1], w0.x, w0.y);
                mma16(acc[q], P0[2], P1[2], P0[3], P1[3], w0.z, w0.w);
                mma16(acc[q], P0[4], P1[4], P0[5], P1[5], w1.x, w1.y);
                mma16(acc[q], P0[6], P1[6], P0[7], P1[7], w1.z, w1.w);
                mma16(acc[q], P0[8], P1[8], P0[9], P1[9], w2.x, w2.y);
            }
        }
    };

    for (int p = 0; p < CHP; p += 2) {
        asm volatile("cp.async.wait_group 1;" ::: "memory");
        __syncthreads();

        consume(p % 5);
        if (p + 3 < CHP) {
            issue(p + 3, (p + 3) % 5);
            asm volatile("cp.async.commit_group;" ::: "memory");
        }
        consume((p + 1) % 5);
        if (p + 4 < CHP) {
            issue(p + 4, (p + 4) % 5);
            asm volatile("cp.async.commit_group;" ::: "memory");
        }
    }

    const int r0 = m0 + row0;
    const int r1 = r0 + 8;
#pragma unroll
    for (int q = 0; q < 13; q++) {
        if (q < cnt) {
            int n0 = (nt0 + q) * 8 + t4 * 2;
            if (r0 < MT) {
                Hout[(size_t)n0 * MT + r0]       = acc[q][0];
                Hout[(size_t)(n0 + 1) * MT + r0] = acc[q][1];
            }
            if (r1 < MT) {
                Hout[(size_t)n0 * MT + r1]       = acc[q][2];
                Hout[(size_t)(n0 + 1) * MT + r1] = acc[q][3];
            }
        }
    }
}

// ---------------------------------------------------------------- layer 3
// S2[b, j*40+i] = sum_d X[b,i,d] * H2[b,j,d]  (f32 accum, one fp16 rounding)
// R12: 4 CTAs per b (j-quarters of 50), grid 2048, 320 threads, 11.4 KB smem.
__global__ __launch_bounds__(320)
void s2_kernel() {
    __shared__ float h2s[50 * 36];                  // 7.2 KB (36-pad)
    __shared__ __align__(16) __half s2s[2000];      // 4 KB
    const int bx  = blockIdx.x;
    const int b   = bx >> 2;
    const int j0  = (bx & 3) * 50;
    const int tid = threadIdx.x;

    for (int idx = tid; idx < 50 * 32; idx += 320) {
        int jl = idx >> 5, d = idx & 31;
        h2s[jl * 36 + d] = g_Ht2[(size_t)(j0 + jl) * MT + b * 32 + d];
    }
    __syncthreads();

    const int i  = tid >> 3;      // 0..39
    const int jg = tid & 7;
    float4 xr[8];
    const float4* xp = (const float4*)(g_Xt + (size_t)i * MT + b * 32);
#pragma unroll
    for (int q = 0; q < 8; q++) xr[q] = xp[q];

#pragma unroll
    for (int t = 0; t < 7; t++) {
        int jl = jg + 8 * t;
        if (jl < 50) {
            const float4* hp = (const float4*)(h2s + jl * 36);
            float s = 0.0f;
#pragma unroll
            for (int w = 0; w < 8; w++) {
                float4 h = hp[w];
                s += xr[w].x * h.x + xr[w].y * h.y + xr[w].z * h.z + xr[w].w * h.w;
            }
            s2s[jl * 40 + i] = __float2half_rn(s);
        }
    }
    __syncthreads();

    const uint4* ss = (const uint4*)s2s;
    uint4* dd = (uint4*)(g_S2 + (size_t)b * 8000 + j0 * 40);
    for (int idx = tid; idx < 250; idx += 320) dd[idx] = ss[idx];
}

// P3[kg][b,n] = sum_{k in group kg} S2[b,k] W2[k,n].
// grid 128: bq = bx>>2 (16 b-rows), kg = bx&3 (25 pairs). 25 warps = nt.
__global__ __launch_bounds__(800, 1)
void final3_kernel() {
    constexpr int ARS = 176;
    extern __shared__ __align__(16) char smem[];
    uint32_t* bstg = (uint32_t*)smem;
    char*     astg = smem + 3 * STG_BB;

    const int tid  = threadIdx.x;
    const int lane = tid & 31;
    const int wid  = tid >> 5;
    const int g    = lane >> 2;
    const int t4   = lane & 3;
    const int b0   = (blockIdx.x >> 2) * 16;
    const int kg   = blockIdx.x & 3;
    const int P0g  = kg * 25;

    const uint32_t uB = smem_u32(bstg);
    const uint32_t uA = smem_u32(astg);

    auto issue = [&](int pl, int s) {
        int p = P0g + pl;
        const char* srcB = (const char*)(g_B2 + (size_t)p * STG_BW);
        uint32_t dB = uB + s * STG_BB;
        for (int t = tid * 16; t < STG_BB; t += 800 * 16)
            cp16(dB + t, srcB + t);
        if (tid < 160) {
            int r = tid / 10, sg = tid - r * 10;
            cp16(uA + s * (16 * ARS) + r * ARS + sg * 16,
                 (const char*)(g_S2 + (size_t)(b0 + r) * 8000 + p * 80) + sg * 16);
        }
    };

    issue(0, 0);
    asm volatile("cp.async.commit_group;" ::: "memory");
    issue(1, 1);
    asm volatile("cp.async.commit_group;" ::: "memory");

    float acc[4] = {0.f, 0.f, 0.f, 0.f};

    for (int pl = 0; pl < 25; pl++) {
        int s = pl % 3;
        asm volatile("cp.async.wait_group 1;" ::: "memory");
        __syncthreads();
        if (pl + 2 < 25) issue(pl + 2, (pl + 2) % 3);
        asm volatile("cp.async.commit_group;" ::: "memory");

        const char* as = astg + s * (16 * ARS);
        uint32_t P0[10], P1[10];
#pragma unroll
        for (int pb = 0; pb < 10; pb++) {
            P0[pb] = *(const uint32_t*)(as + g * ARS       + (pb * 8 + 2 * t4) * 2);
            P1[pb] = *(const uint32_t*)(as + (g + 8) * ARS + (pb * 8 + 2 * t4) * 2);
        }
        const uint4* bw = (const uint4*)(bstg + s * STG_BW + (wid * 32 + lane) * 12);
        uint4 w0 = bw[0], w1 = bw[1], w2 = bw[2];
        mma16(acc, P0[0], P1[0], P0[1], P1[1], w0.x, w0.y);
        mma16(acc, P0[2], P1[2], P0[3], P1[3], w0.z, w0.w);
        mma16(acc, P0[4], P1[4], P0[5], P1[5], w1.x, w1.y);
        mma16(acc, P0[6], P1[6], P0[7], P1[7], w1.z, w1.w);
        mma16(acc, P0[8], P1[8], P0[9], P1[9], w2.x, w2.y);
    }

    const int n0 = wid * 8 + t4 * 2;
    float* P = g_P3 + (size_t)kg * 512 * 200;
    P[(size_t)(b0 + g) * 200 + n0]         = acc[0];
    P[(size_t)(b0 + g) * 200 + n0 + 1]     = acc[1];
    P[(size_t)(b0 + g + 8) * 200 + n0]     = acc[2];
    P[(size_t)(b0 + g + 8) * 200 + n0 + 1] = acc[3];
}

// ---------------------------------------------------------------- reduction
__global__ void reduce_out_kernel(float* __restrict__ out) {
    int idx = blockIdx.x * blockDim.x + threadIdx.x;
    if (idx >= 512 * 600) return;
    int b = idx / 600, no = idx - b * 600;
    float s = 0.0f;
    if (no < 400) {
        const float* H = (no < 200) ? g_Ht1 : g_Ht2;
        int n = no % 200;
        const float4* p = (const float4*)(H + (size_t)n * MT + b * 32);
#pragma unroll
        for (int q = 0; q < 8; q++) {
            float4 v = p[q];
            s += v.x + v.y + v.z + v.w;
        }
    } else {
        int n = no - 400;
#pragma unroll
        for (int kg = 0; kg < 4; kg++)
            s += g_P3[(size_t)kg * 512 * 200 + (size_t)b * 200 + n];
    }
    out[idx] = s;
}

// ---------------------------------------------------------------- launch
extern "C" void kernel_launch(void* const* d_in, const int* in_sizes, int n_in,
                              void* d_out, int out_size) {
    const float* inp = (const float*)d_in[0];
    const float* W0  = (const float*)d_in[1];
    const float* W1  = (const float*)d_in[2];
    const float* W2  = (const float*)d_in[3];
    float* out = (float*)d_out;

    void *pXt, *pH1, *pH2, *pB0, *pB1, *pB2;
    cudaGetSymbolAddress(&pXt, g_Xt);
    cudaGetSymbolAddress(&pH1, g_Ht1);
    cudaGetSymbolAddress(&pH2, g_Ht2);
    cudaGetSymbolAddress(&pB0, g_B0);
    cudaGetSymbolAddress(&pB1, g_B1);
    cudaGetSymbolAddress(&pB2, g_B2);
    float*    Xt = (float*)pXt;
    float*    H1 = (float*)pH1;
    float*    H2 = (float*)pH2;
    uint32_t* B0 = (uint32_t*)pB0;
    uint32_t* B1 = (uint32_t*)pB1;
    uint32_t* B2 = (uint32_t*)pB2;

    const int SMEM  = 5 * STG_BB + 17920 + 4480;   // 214400 B
    const int SMEM3 = 3 * STG_BB + 3 * 16 * 176;   // 123648 B
    cudaFuncSetAttribute(cin_fp16_layer<40>,
                         cudaFuncAttributeMaxDynamicSharedMemorySize, SMEM);
    cudaFuncSetAttribute(cin_fp16_layer<200>,
                         cudaFuncAttributeMaxDynamicSharedMemorySize, SMEM);
    cudaFuncSetAttribute(final3_kernel,
                         cudaFuncAttributeMaxDynamicSharedMemorySize, SMEM3);

    const int prep_total = F0 * MT + 220 * STG_BW;
    prep_all_kernel<<<(prep_total + 255) / 256, 256>>>(inp, W0, W1, W2, B0, B1, B2);

    cin_fp16_layer<40> <<<GRID, 512, SMEM>>>(Xt, B0, H1);
    cin_fp16_layer<200><<<GRID, 512, SMEM>>>(H1, B1, H2);

    s2_kernel<<<2048, 320>>>();
    final3_kernel<<<128, 800, SMEM3>>>();

    reduce_out_kernel<<<(512 * 600 + 255) / 256, 256>>>(out);
}

// round 14
// speedup vs baseline: 1.0732x; 1.0732x over previous
#include <cuda_runtime.h>
#include <cuda_fp16.h>
#include <cstdint>

// ===========================================================================
// CIN (xDeepFM) on GB300 via mma.sync fp16 (f32 accum).
// Layers 1-2: generated-A GEMM at M=16384 (chunk-paired K=80 = 5 x m16n8k16,
//   147 CTAs / BM=112 / 16 warps, R8 warp table; 5-stage cp.async pipeline,
//   one wait+syncthreads per TWO pairs).
// Layer 3 collapsed: out3[b,n] = sum_k S2[b,k] W2[k,n],
//   S2[b, j*40+i] = sum_d X[b,i,d] H2[b,j,d].
//   R13: S2 computed via mma.sync (per-b GEMM X_b[40x32] . H2_b^T[32x200],
//   150 mma16/b) — the scalar s2 kernel was instruction-bound at ~40 us.
//   final3 = M=512 GEMM, 4-way K-split, f32 partials summed in reduce_out.
// ===========================================================================

constexpr int MT  = 16384;
constexpr int F0  = 40;
constexpr int BM  = 112;
constexpr int NT  = 25;

constexpr int STG_BW   = NT * 32 * 12;        // B words per pair-stage = 9600
constexpr int STG_BB   = STG_BW * 4;          // 38400 B
constexpr int GRID     = 147;

__device__ float g_Xt [F0  * MT + 256];
__device__ float g_Ht1[200 * MT + 256];
__device__ float g_Ht2[200 * MT + 256];
__device__ __align__(16) __half g_S2[512 * 8000];
__device__ float g_P3[4 * 512 * 200];
__device__ __align__(16) uint32_t g_B0[20  * STG_BW];
__device__ __align__(16) uint32_t g_B1[100 * STG_BW];
__device__ __align__(16) uint32_t g_B2[100 * STG_BW];

// R8 warp table: (m16 tile, nt0, cnt); SMSP unit sums (wid%4): 45,45,43,42
__constant__ int c_tile[16] = {2,3,4,5, 2,3,6,4, 5,6,0,1, 0,0,1,1};
__constant__ int c_nt0 [16] = {0,0,0,0, 13,13,0,13, 13,13,0,0, 9,17,9,17};
__constant__ int c_cnt [16] = {13,13,13,13, 12,12,13,12, 12,12,9,9, 8,8,8,8};

// ---------------------------------------------------------------- helpers
__device__ __forceinline__ uint32_t smem_u32(const void* p) {
    uint32_t a;
    asm("{ .reg .u64 t; cvta.to.shared.u64 t, %1; cvt.u32.u64 %0, t; }"
        : "=r"(a) : "l"(p));
    return a;
}

__device__ __forceinline__ uint32_t pack_h2(float lo, float hi) {
    uint32_t u;
    asm("cvt.rn.f16x2.f32 %0, %1, %2;" : "=r"(u) : "f"(hi), "f"(lo));
    return u;
}

__device__ __forceinline__ void cp16(uint32_t dst_smem, const void* src) {
    asm volatile("cp.async.cg.shared.global [%0], [%1], 16;"
                 :: "r"(dst_smem), "l"(src) : "memory");
}

__device__ __forceinline__ void mma16(float* d,
                                      uint32_t a0, uint32_t a1, uint32_t a2, uint32_t a3,
                                      uint32_t b0, uint32_t b1) {
    asm volatile(
        "mma.sync.aligned.m16n8k16.row.col.f32.f16.f16.f32 "
        "{%0,%1,%2,%3}, {%4,%5,%6,%7}, {%8,%9}, {%0,%1,%2,%3};"
        : "+f"(d[0]), "+f"(d[1]), "+f"(d[2]), "+f"(d[3])
        : "r"(a0), "r"(a1), "r"(a2), "r"(a3), "r"(b0), "r"(b1));
}

// ---------------------------------------------------------------- fused prep
__global__ void prep_all_kernel(const float* __restrict__ inp,
                                const float* __restrict__ W0,
                                const float* __restrict__ W1,
                                const float* __restrict__ W2,
                                uint32_t* __restrict__ B0,
                                uint32_t* __restrict__ B1,
                                uint32_t* __restrict__ B2) {
    int idx = blockIdx.x * blockDim.x + threadIdx.x;
    if (idx < F0 * MT) {
        int i = idx >> 14;
        int m = idx & (MT - 1);
        int b = m >> 5, d = m & 31;
        g_Xt[idx] = inp[b * (F0 * 32) + i * 32 + d];
        return;
    }
    idx -= F0 * MT;
    if (idx >= 220 * STG_BW) return;
    int v = idx % 12;
    int t = idx / 12;
    int lane = t & 31; t >>= 5;
    int nt   = t % NT;
    int pg   = t / NT;

    const float* W; uint32_t* blob; int FI, p;
    if (pg < 20)       { W = W0; blob = B0; FI = 40;  p = pg; }
    else if (pg < 120) { W = W1; blob = B1; FI = 200; p = pg - 20; }
    else               { W = W2; blob = B2; FI = 200; p = pg - 120; }

    uint32_t word = 0;
    if (v < 10) {
        int u = (v < 5) ? v : v - 5;
        int j = 2 * p + (v >= 5);
        int n  = nt * 8 + (lane >> 2);
        int i0 = u * 8 + (lane & 3) * 2;
        float lo = __ldg(&W[((size_t)i0 * FI + j) * 200 + n]);
        float hi = __ldg(&W[((size_t)(i0 + 1) * FI + j) * 200 + n]);
        word = pack_h2(lo, hi);
    }
    blob[(((size_t)p * NT + nt) * 32 + lane) * 12 + v] = word;
}

// ---------------------------------------------------------------- layer 1/2
// smem: bstg 5*38400 | xs[BM][40] 17920 | hstg[5][2][BM] 4480  = 214400 B
template <int CH>
__global__ __launch_bounds__(512, 1)
void cin_fp16_layer(const float* __restrict__ Hprev,    // [CH][MT]
                    const uint32_t* __restrict__ blob,  // [CHP][STG_BW]
                    float* __restrict__ Hout)           // [200][MT]
{
    constexpr int CHP = CH / 2;
    extern __shared__ __align__(16) char smem[];
    uint32_t* bstg = (uint32_t*)smem;
    float*    xs   = (float*)(smem + 5 * STG_BB);
    float*    hstg = (float*)(smem + 5 * STG_BB + 17920);

    const int tid  = threadIdx.x;
    const int lane = tid & 31;
    const int wid  = tid >> 5;
    const int g    = lane >> 2;
    const int t4   = lane & 3;
    const int m0   = blockIdx.x * BM;

    const int tile = c_tile[wid];
    const int nt0  = c_nt0[wid];
    const int cnt  = c_cnt[wid];
    const int row0 = tile * 16 + g;

    for (int idx = tid; idx < BM * 40; idx += 512) {
        int ml = idx / 40, i = idx - ml * 40;
        int gr = m0 + ml; if (gr > MT - 1) gr = MT - 1;
        xs[ml * 40 + i] = g_Xt[i * MT + gr];
    }

    const uint32_t uB = smem_u32(bstg);
    const uint32_t uH = smem_u32(hstg);

    auto issue = [&](int p, int s) {
        const char* srcB = (const char*)(blob + (size_t)p * STG_BW);
        uint32_t dB = uB + s * STG_BB;
        for (int t = tid * 16; t < STG_BB; t += 512 * 16)
            cp16(dB + t, srcB + t);
        if (tid < 56) {
            int cc = tid / 28, q = tid - cc * 28;
            cp16(uH + s * (2 * BM * 4) + cc * (BM * 4) + q * 16,
                 (const char*)(Hprev + (size_t)(2 * p + cc) * MT + m0) + q * 16);
        }
    };

    issue(0, 0);
    asm volatile("cp.async.commit_group;" ::: "memory");
    issue(1, 1);
    asm volatile("cp.async.commit_group;" ::: "memory");
    issue(2, 2);
    asm volatile("cp.async.commit_group;" ::: "memory");

    float acc[13][4];
#pragma unroll
    for (int q = 0; q < 13; q++)
#pragma unroll
        for (int c = 0; c < 4; c++) acc[q][c] = 0.0f;

    auto consume = [&](int s) {
        const float* hp = hstg + s * (2 * BM);
        const float hA0 = hp[row0],      hA1 = hp[row0 + 8];
        const float hB0 = hp[BM + row0], hB1 = hp[BM + row0 + 8];

        uint32_t P0[10], P1[10];
#pragma unroll
        for (int pb = 0; pb < 5; pb++) {
            const int ib = pb * 8 + 2 * t4;
            float2 x0 = *(const float2*)(xs + row0 * 40 + ib);
            float2 x1 = *(const float2*)(xs + (row0 + 8) * 40 + ib);
            P0[pb]     = pack_h2(x0.x * hA0, x0.y * hA0);
            P1[pb]     = pack_h2(x1.x * hA1, x1.y * hA1);
            P0[5 + pb] = pack_h2(x0.x * hB0, x0.y * hB0);
            P1[5 + pb] = pack_h2(x1.x * hB1, x1.y * hB1);
        }

        const uint32_t* bs = bstg + s * STG_BW;
#pragma unroll
        for (int q = 0; q < 13; q++) {
            if (q < cnt) {
                const uint4* bw = (const uint4*)(bs + ((nt0 + q) * 32 + lane) * 12);
                uint4 w0 = bw[0], w1 = bw[1], w2 = bw[2];
                mma16(acc[q], P0[0], P1[0], P0[1], P1[1], w0.x, w0.y);
                mma16(acc[q], P0[2], P1[2], P0[3], P1[3], w0.z, w0.w);
                mma16(acc[q], P0[4], P1[4], P0[5], P1[5], w1.x, w1.y);
                mma16(acc[q], P0[6], P1[6], P0[7], P1[7], w1.z, w1.w);
                mma16(acc[q], P0[8], P1[8], P0[9], P1[9], w2.x, w2.y);
            }
        }
    };

    for (int p = 0; p < CHP; p += 2) {
        asm volatile("cp.async.wait_group 1;" ::: "memory");
        __syncthreads();

        consume(p % 5);
        if (p + 3 < CHP) {
            issue(p + 3, (p + 3) % 5);
            asm volatile("cp.async.commit_group;" ::: "memory");
        }
        consume((p + 1) % 5);
        if (p + 4 < CHP) {
            issue(p + 4, (p + 4) % 5);
            asm volatile("cp.async.commit_group;" ::: "memory");
        }
    }

    const int r0 = m0 + row0;
    const int r1 = r0 + 8;
#pragma unroll
    for (int q = 0; q < 13; q++) {
        if (q < cnt) {
            int n0 = (nt0 + q) * 8 + t4 * 2;
            if (r0 < MT) {
                Hout[(size_t)n0 * MT + r0]       = acc[q][0];
                Hout[(size_t)(n0 + 1) * MT + r0] = acc[q][1];
            }
            if (r1 < MT) {
                Hout[(size_t)n0 * MT + r1]       = acc[q][2];
                Hout[(size_t)(n0 + 1) * MT + r1] = acc[q][3];
            }
        }
    }
}

// ---------------------------------------------------------------- layer 3 (S2)
// S2[b, j*40+i] = sum_d X[b,i,d] H2[b,j,d]  ==  per-b GEMM via mma.sync:
//   A = X_b [40(i) x 32(d)] row-major, B = H2_b [200(j) x 32(d)] "col-major",
//   3 m16-tiles x 25 n8-tiles x 2 k16.  Grid 512 (one b), 96 threads (3 warps,
//   nt stride 3, B-words prefetched one nt ahead).  Result staged in smem,
//   dumped coalesced in g_S2's [b][j][i] half layout (final3-compatible).
__global__ __launch_bounds__(96)
void s2_mma_kernel() {
    __shared__ __align__(16) __half s2s[8000];
    const int b    = blockIdx.x;
    const int tid  = threadIdx.x;
    const int lane = tid & 31;
    const int wid  = tid >> 5;
    const int g    = lane >> 2;
    const int t4   = lane & 3;

    // A fragment words: aw[mt][r][u], row i = mt*16 + r*8 + g, k-pair u*8+2t4.
    // Invalid only for (mt==2, r==1) (i >= 40) -> zero.
    uint32_t aw[3][2][4];
#pragma unroll
    for (int mt = 0; mt < 3; mt++)
#pragma unroll
        for (int r = 0; r < 2; r++) {
            int i = mt * 16 + r * 8 + g;
#pragma unroll
            for (int u = 0; u < 4; u++) {
                if (mt == 2 && r == 1) { aw[mt][r][u] = 0; }
                else {
                    float2 v = *(const float2*)(g_Xt + (size_t)i * MT + b * 32 + u * 8 + 2 * t4);
                    aw[mt][r][u] = pack_h2(v.x, v.y);
                }
            }
        }

    auto loadB = [&](int nt, uint32_t* bw) {
        int j = nt * 8 + g;
#pragma unroll
        for (int u = 0; u < 4; u++) {
            float2 v = *(const float2*)(g_Ht2 + (size_t)j * MT + b * 32 + u * 8 + 2 * t4);
            bw[u] = pack_h2(v.x, v.y);
        }
    };

    uint32_t bw[4];
    loadB(wid, bw);
    for (int nt = wid; nt < 25; nt += 3) {
        uint32_t bn[4];
        if (nt + 3 < 25) loadB(nt + 3, bn);

        const int n0 = nt * 8 + 2 * t4;
#pragma unroll
        for (int mt = 0; mt < 3; mt++) {
            float acc[4] = {0.f, 0.f, 0.f, 0.f};
            mma16(acc, aw[mt][0][0], aw[mt][1][0], aw[mt][0][1], aw[mt][1][1], bw[0], bw[1]);
            mma16(acc, aw[mt][0][2], aw[mt][1][2], aw[mt][0][3], aw[mt][1][3], bw[2], bw[3]);
            const int i0 = mt * 16 + g;        // always < 40
            s2s[n0 * 40 + i0]       = __float2half_rn(acc[0]);
            s2s[(n0 + 1) * 40 + i0] = __float2half_rn(acc[1]);
            if (mt < 2) {                       // i1 = i0+8 < 40 only for mt<2
                s2s[n0 * 40 + i0 + 8]       = __float2half_rn(acc[2]);
                s2s[(n0 + 1) * 40 + i0 + 8] = __float2half_rn(acc[3]);
            }
        }
#pragma unroll
        for (int u = 0; u < 4; u++) bw[u] = bn[u];
    }
    __syncthreads();

    const uint4* ss = (const uint4*)s2s;
    uint4* dd = (uint4*)(g_S2 + (size_t)b * 8000);
    for (int idx = tid; idx < 1000; idx += 96) dd[idx] = ss[idx];
}

// P3[kg][b,n] = sum_{k in group kg} S2[b,k] W2[k,n].
// grid 128: bq = bx>>2 (16 b-rows), kg = bx&3 (25 pairs). 25 warps = nt.
__global__ __launch_bounds__(800, 1)
void final3_kernel() {
    constexpr int ARS = 176;
    extern __shared__ __align__(16) char smem[];
    uint32_t* bstg = (uint32_t*)smem;
    char*     astg = smem + 3 * STG_BB;

    const int tid  = threadIdx.x;
    const int lane = tid & 31;
    const int wid  = tid >> 5;
    const int g    = lane >> 2;
    const int t4   = lane & 3;
    const int b0   = (blockIdx.x >> 2) * 16;
    const int kg   = blockIdx.x & 3;
    const int P0g  = kg * 25;

    const uint32_t uB = smem_u32(bstg);
    const uint32_t uA = smem_u32(astg);

    auto issue = [&](int pl, int s) {
        int p = P0g + pl;
        const char* srcB = (const char*)(g_B2 + (size_t)p * STG_BW);
        uint32_t dB = uB + s * STG_BB;
        for (int t = tid * 16; t < STG_BB; t += 800 * 16)
            cp16(dB + t, srcB + t);
        if (tid < 160) {
            int r = tid / 10, sg = tid - r * 10;
            cp16(uA + s * (16 * ARS) + r * ARS + sg * 16,
                 (const char*)(g_S2 + (size_t)(b0 + r) * 8000 + p * 80) + sg * 16);
        }
    };

    issue(0, 0);
    asm volatile("cp.async.commit_group;" ::: "memory");
    issue(1, 1);
    asm volatile("cp.async.commit_group;" ::: "memory");

    float acc[4] = {0.f, 0.f, 0.f, 0.f};

    for (int pl = 0; pl < 25; pl++) {
        int s = pl % 3;
        asm volatile("cp.async.wait_group 1;" ::: "memory");
        __syncthreads();
        if (pl + 2 < 25) issue(pl + 2, (pl + 2) % 3);
        asm volatile("cp.async.commit_group;" ::: "memory");

        const char* as = astg + s * (16 * ARS);
        uint32_t P0[10], P1[10];
#pragma unroll
        for (int pb = 0; pb < 10; pb++) {
            P0[pb] = *(const uint32_t*)(as + g * ARS       + (pb * 8 + 2 * t4) * 2);
            P1[pb] = *(const uint32_t*)(as + (g + 8) * ARS + (pb * 8 + 2 * t4) * 2);
        }
        const uint4* bw = (const uint4*)(bstg + s * STG_BW + (wid * 32 + lane) * 12);
        uint4 w0 = bw[0], w1 = bw[1], w2 = bw[2];
        mma16(acc, P0[0], P1[0], P0[1], P1[1], w0.x, w0.y);
        mma16(acc, P0[2], P1[2], P0[3], P1[3], w0.z, w0.w);
        mma16(acc, P0[4], P1[4], P0[5], P1[5], w1.x, w1.y);
        mma16(acc, P0[6], P1[6], P0[7], P1[7], w1.z, w1.w);
        mma16(acc, P0[8], P1[8], P0[9], P1[9], w2.x, w2.y);
    }

    const int n0 = wid * 8 + t4 * 2;
    float* P = g_P3 + (size_t)kg * 512 * 200;
    P[(size_t)(b0 + g) * 200 + n0]         = acc[0];
    P[(size_t)(b0 + g) * 200 + n0 + 1]     = acc[1];
    P[(size_t)(b0 + g + 8) * 200 + n0]     = acc[2];
    P[(size_t)(b0 + g + 8) * 200 + n0 + 1] = acc[3];
}

// ---------------------------------------------------------------- reduction
__global__ void reduce_out_kernel(float* __restrict__ out) {
    int idx = blockIdx.x * blockDim.x + threadIdx.x;
    if (idx >= 512 * 600) return;
    int b = idx / 600, no = idx - b * 600;
    float s = 0.0f;
    if (no < 400) {
        const float* H = (no < 200) ? g_Ht1 : g_Ht2;
        int n = no % 200;
        const float4* p = (const float4*)(H + (size_t)n * MT + b * 32);
#pragma unroll
        for (int q = 0; q < 8; q++) {
            float4 v = p[q];
            s += v.x + v.y + v.z + v.w;
        }
    } else {
        int n = no - 400;
#pragma unroll
        for (int kg = 0; kg < 4; kg++)
            s += g_P3[(size_t)kg * 512 * 200 + (size_t)b * 200 + n];
    }
    out[idx] = s;
}

// ---------------------------------------------------------------- launch
extern "C" void kernel_launch(void* const* d_in, const int* in_sizes, int n_in,
                              void* d_out, int out_size) {
    const float* inp = (const float*)d_in[0];
    const float* W0  = (const float*)d_in[1];
    const float* W1  = (const float*)d_in[2];
    const float* W2  = (const float*)d_in[3];
    float* out = (float*)d_out;

    void *pXt, *pH1, *pH2, *pB0, *pB1, *pB2;
    cudaGetSymbolAddress(&pXt, g_Xt);
    cudaGetSymbolAddress(&pH1, g_Ht1);
    cudaGetSymbolAddress(&pH2, g_Ht2);
    cudaGetSymbolAddress(&pB0, g_B0);
    cudaGetSymbolAddress(&pB1, g_B1);
    cudaGetSymbolAddress(&pB2, g_B2);
    float*    Xt = (float*)pXt;
    float*    H1 = (float*)pH1;
    float*    H2 = (float*)pH2;
    uint32_t* B0 = (uint32_t*)pB0;
    uint32_t* B1 = (uint32_t*)pB1;
    uint32_t* B2 = (uint32_t*)pB2;

    const int SMEM  = 5 * STG_BB + 17920 + 4480;   // 214400 B
    const int SMEM3 = 3 * STG_BB + 3 * 16 * 176;   // 123648 B
    cudaFuncSetAttribute(cin_fp16_layer<40>,
                         cudaFuncAttributeMaxDynamicSharedMemorySize, SMEM);
    cudaFuncSetAttribute(cin_fp16_layer<200>,
                         cudaFuncAttributeMaxDynamicSharedMemorySize, SMEM);
    cudaFuncSetAttribute(final3_kernel,
                         cudaFuncAttributeMaxDynamicSharedMemorySize, SMEM3);

    const int prep_total = F0 * MT + 220 * STG_BW;
    prep_all_kernel<<<(prep_total + 255) / 256, 256>>>(inp, W0, W1, W2, B0, B1, B2);

    cin_fp16_layer<40> <<<GRID, 512, SMEM>>>(Xt, B0, H1);
    cin_fp16_layer<200><<<GRID, 512, SMEM>>>(H1, B1, H2);

    s2_mma_kernel<<<512, 96>>>();
    final3_kernel<<<128, 800, SMEM3>>>();

    reduce_out_kernel<<<(512 * 600 + 255) / 256, 256>>>(out);
}